// round 6
// baseline (speedup 1.0000x reference)
#include <cuda_runtime.h>
#include <cuda_bf16.h>

// BatchRNNCustom: pack padded (B,S,D) sequences by descending length.
// Output layout (fp32, concatenated in reference return order):
//   [0, B*S*D)    packed_data
//   [.. +S)       batch_sizes
//   [.. +B)       sorted_indices
//   [.. +B)       unsorted_indices
//
// SINGLE fused kernel. Every block independently:
//   1) reads the 64 lengths (256 B, L2-hot), dtype-detects int32 vs int64,
//   2) stable descending rank-sort (O(B^2), 64 threads),
//   3) suffix sums suf[k] = sum_{j>=k} slen[j],
//   4) band table Rs[k] = (slen[k]+1)*k + suf[k]  (slen[64] := -1 sentinel),
//      prefix-min Mn[k] (ties bump Rs by +1; prefix-min restores a
//      searchable monotone sequence — first k with Mn[k] <= r has Rs[k]=Mn[k]),
//   5) for each of its rows r: m = smallest k with Mn[k] <= r,
//      t = (r - suf[m]) / m,  b = r - suf[m] - t*m,  src = sidx[b],
//   6) streams 16 rows (32 KB) with MLP=8 float4 loads/stores (.cs).
// Rows >= total get zeros. Block 0 also writes the aux outputs.

#define BB 64
#define SS 2048
#define DD 512
#define RPB 16          // rows per block
#define NTHR 256

__global__ void __launch_bounds__(NTHR) fused_pack_kernel(
        const float* __restrict__ in,
        const int* __restrict__ lengths_raw,
        float* __restrict__ out, long long out_size) {
    __shared__ int sraw[BB];        // lengths by original index
    __shared__ int slen[BB + 1];    // sorted descending; slen[64] = -1 sentinel
    __shared__ int sidx[BB];        // rank -> original batch index
    __shared__ int suf[BB + 1];     // suffix sums of slen
    __shared__ int Rs[BB + 1];      // band-start rows
    __shared__ int Mn[BB + 1];      // prefix-min of Rs
    __shared__ int s_is64;
    __shared__ int2 rowinfo[RPB];   // {t, src}; t = -1 -> zero row

    const int tid = threadIdx.x;

    // ---- dtype detect: lengths >= 1, int64 (LE) has all odd words == 0 ----
    if (tid == 0) s_is64 = 1;
    __syncthreads();
    if (tid < BB) {
        int w = lengths_raw[tid];
        if ((tid & 1) && w != 0) atomicAnd(&s_is64, 0);
    }
    __syncthreads();
    if (tid < BB) {
        sraw[tid] = s_is64 ? (int)((const long long*)lengths_raw)[tid]
                           : lengths_raw[tid];
    }
    __syncthreads();

    // ---- stable descending rank sort ----
    if (tid < BB) {
        int li = sraw[tid];
        int r = 0;
#pragma unroll 8
        for (int j = 0; j < BB; j++) {
            int lj = sraw[j];
            if (lj > li || (lj == li && j < tid)) r++;
        }
        slen[r] = li;
        sidx[r] = tid;
    }
    if (tid == BB) slen[BB] = -1;   // sentinel
    __syncthreads();

    // ---- suffix sums + band-start table (same thread: no extra sync) ----
    if (tid <= BB) {
        int s = 0;
        for (int j = tid; j < BB; j++) s += slen[j];
        suf[tid] = s;
        Rs[tid] = (slen[tid] + 1) * tid + s;
    }
    __syncthreads();

    // ---- prefix-min of Rs ----
    if (tid <= BB) {
        int m = Rs[0];
        for (int j = 1; j <= tid; j++) m = min(m, Rs[j]);
        Mn[tid] = m;
    }
    __syncthreads();

    // ---- per-row inversion: r -> (t, src) ----
    const int r0 = blockIdx.x * RPB;
    const int total = suf[0];
    if (tid < RPB) {
        int r = r0 + tid;
        int2 info = make_int2(-1, -1);
        if (r < total) {
            int lo = 0, hi = BB;            // smallest k with Mn[k] <= r
            while (lo < hi) {
                int mid = (lo + hi) >> 1;
                if (Mn[mid] <= r) hi = mid; else lo = mid + 1;
            }
            int m = lo;                     // m >= 1 for any valid row
            int t = (r - suf[m]) / m;
            int b = r - suf[m] - t * m;
            info = make_int2(t, sidx[b]);
        }
        rowinfo[tid] = info;
    }

    // ---- block 0: aux outputs (overlaps other blocks' streaming) ----
    if (blockIdx.x == 0) {
        const long long base = (long long)BB * SS * DD;
        if (out_size >= base + SS + 2 * BB) {
            for (int t = tid; t < SS; t += NTHR) {
                int t1 = t + 1;             // batch_sizes[t] = #{slen >= t+1}
                int lo = 0, hi = BB;
                while (lo < hi) {
                    int mid = (lo + hi) >> 1;
                    if (slen[mid] >= t1) lo = mid + 1; else hi = mid;
                }
                out[base + t] = (float)lo;
            }
            if (tid < BB) {
                out[base + SS + tid] = (float)sidx[tid];          // sorted
                out[base + SS + BB + sidx[tid]] = (float)tid;     // unsorted
            }
        }
    }
    __syncthreads();

    // ---- payload: 16 rows, 256 threads, MLP=8 float4 per thread ----
    const int th = tid >> 7;        // row-pair selector (0/1)
    const int tl = tid & 127;       // float4 lane within row
    const float4* inp = reinterpret_cast<const float4*>(in);

    float4 v[8];
#pragma unroll
    for (int i = 0; i < 8; i++) {
        int2 m = rowinfo[2 * i + th];
        if (m.x >= 0) {
            long long srow = (long long)m.y * SS + m.x;
            v[i] = __ldcs(inp + srow * (DD / 4) + tl);
        } else {
            v[i] = make_float4(0.f, 0.f, 0.f, 0.f);
        }
    }

    float4* op = reinterpret_cast<float4*>(out) + (long long)r0 * (DD / 4);
#pragma unroll
    for (int i = 0; i < 8; i++)
        __stcs(op + (long long)(2 * i + th) * (DD / 4) + tl, v[i]);
}

extern "C" void kernel_launch(void* const* d_in, const int* in_sizes, int n_in,
                              void* d_out, int out_size) {
    const float* inputs = (const float*)d_in[0];    // (B, S, D) fp32
    // d_in[1]: input_paddings (unused — all zeros)
    const int* lengths_raw = (const int*)d_in[2];   // (B,) int32 or int64
    float* out = (float*)d_out;

    fused_pack_kernel<<<(BB * SS) / RPB, NTHR>>>(inputs, lengths_raw, out,
                                                 (long long)out_size);
}

// round 8
// speedup vs baseline: 1.0576x; 1.0576x over previous
#include <cuda_runtime.h>
#include <cuda_bf16.h>

// BatchRNNCustom: pack padded (B,S,D) sequences by descending length.
// Output layout (fp32, concatenated in reference return order):
//   [0, B*S*D)    packed_data
//   [.. +S)       batch_sizes
//   [.. +B)       sorted_indices
//   [.. +B)       unsorted_indices
//
// SINGLE fused kernel, 2048 blocks x 512 threads, 64 rows (128 KB) per block.
// Each block independently recomputes the tiny metadata (256 B read, O(B^2)
// over 64 threads — amortized over 128 KB of streaming), then analytically
// inverts row -> (t, src_batch):
//   slen sorted desc, suf[k] = sum_{j>=k} slen[j]
//   Rs[k] = (slen[k]+1)*k + suf[k], Mn = prefix-min(Rs)  (handles ties)
//   m = first k with Mn[k] <= r;  t = (r - suf[m])/m;  b = r - suf[m] - t*m
// Rows >= total are zeroed. Block 0 writes the aux outputs.

#define BB 64
#define SS 2048
#define DD 512
#define RPB 64          // rows per block
#define NTHR 512

__global__ void __launch_bounds__(NTHR) fused_pack_kernel(
        const float* __restrict__ in,
        const int* __restrict__ lengths_raw,
        float* __restrict__ out, long long out_size) {
    __shared__ int sraw[BB];        // lengths by original index
    __shared__ int slen[BB + 1];    // sorted descending; slen[64] = -1 sentinel
    __shared__ int sidx[BB];        // rank -> original batch index
    __shared__ int suf[BB + 1];     // suffix sums of slen
    __shared__ int Rs[BB + 1];      // band-start rows
    __shared__ int Mn[BB + 1];      // prefix-min of Rs
    __shared__ int s_is64;
    __shared__ int2 rowinfo[RPB];   // {t, src}; t = -1 -> zero row

    const int tid = threadIdx.x;

    // ---- dtype detect: lengths >= 1, int64 (LE) has all odd words == 0 ----
    if (tid == 0) s_is64 = 1;
    __syncthreads();
    if (tid < BB) {
        int w = lengths_raw[tid];
        if ((tid & 1) && w != 0) atomicAnd(&s_is64, 0);
    }
    __syncthreads();
    if (tid < BB) {
        sraw[tid] = s_is64 ? (int)((const long long*)lengths_raw)[tid]
                           : lengths_raw[tid];
    }
    __syncthreads();

    // ---- stable descending rank sort (64 threads, O(B) each) ----
    if (tid < BB) {
        int li = sraw[tid];
        int r = 0;
#pragma unroll 8
        for (int j = 0; j < BB; j++) {
            int lj = sraw[j];
            if (lj > li || (lj == li && j < tid)) r++;
        }
        slen[r] = li;
        sidx[r] = tid;
    }
    if (tid == BB) slen[BB] = -1;   // sentinel
    __syncthreads();

    // ---- suffix sums + band-start table ----
    if (tid <= BB) {
        int s = 0;
        for (int j = tid; j < BB; j++) s += slen[j];
        suf[tid] = s;
        Rs[tid] = (slen[tid] + 1) * tid + s;
    }
    __syncthreads();

    // ---- prefix-min of Rs ----
    if (tid <= BB) {
        int m = Rs[0];
        for (int j = 1; j <= tid; j++) m = min(m, Rs[j]);
        Mn[tid] = m;
    }
    __syncthreads();

    // ---- per-row inversion: r -> (t, src), 64 threads, 1 row each ----
    const int r0 = blockIdx.x * RPB;
    const int total = suf[0];
    if (tid < RPB) {
        int r = r0 + tid;
        int2 info = make_int2(-1, -1);
        if (r < total) {
            int lo = 0, hi = BB;            // smallest k with Mn[k] <= r
            while (lo < hi) {
                int mid = (lo + hi) >> 1;
                if (Mn[mid] <= r) hi = mid; else lo = mid + 1;
            }
            int m = lo;                     // m >= 1 for any valid row
            int t = (r - suf[m]) / m;
            int b = r - suf[m] - t * m;
            info = make_int2(t, sidx[b]);
        }
        rowinfo[tid] = info;
    }

    // ---- block 0: aux outputs ----
    if (blockIdx.x == 0) {
        const long long base = (long long)BB * SS * DD;
        if (out_size >= base + SS + 2 * BB) {
            for (int t = tid; t < SS; t += NTHR) {
                int t1 = t + 1;             // batch_sizes[t] = #{slen >= t+1}
                int lo = 0, hi = BB;
                while (lo < hi) {
                    int mid = (lo + hi) >> 1;
                    if (slen[mid] >= t1) lo = mid + 1; else hi = mid;
                }
                out[base + t] = (float)lo;
            }
            if (tid < BB) {
                out[base + SS + tid] = (float)sidx[tid];          // sorted
                out[base + SS + BB + sidx[tid]] = (float)tid;     // unsorted
            }
        }
    }
    __syncthreads();

    // ---- payload: 64 rows, 512 threads, 2 batches of MLP=8 float4 ----
    const int th = tid >> 7;        // row-slot within group of 4 (0..3)
    const int tl = tid & 127;       // float4 lane within row
    const float4* inp = reinterpret_cast<const float4*>(in);
    float4* op = reinterpret_cast<float4*>(out) + (long long)r0 * (DD / 4);

#pragma unroll
    for (int batch = 0; batch < 2; batch++) {
        float4 v[8];
#pragma unroll
        for (int j = 0; j < 8; j++) {
            int row = batch * 32 + j * 4 + th;
            int2 m = rowinfo[row];
            if (m.x >= 0) {
                long long srow = (long long)m.y * SS + m.x;
                v[j] = __ldcs(inp + srow * (DD / 4) + tl);
            } else {
                v[j] = make_float4(0.f, 0.f, 0.f, 0.f);
            }
        }
#pragma unroll
        for (int j = 0; j < 8; j++) {
            int row = batch * 32 + j * 4 + th;
            __stcs(op + (long long)row * (DD / 4) + tl, v[j]);
        }
    }
}

extern "C" void kernel_launch(void* const* d_in, const int* in_sizes, int n_in,
                              void* d_out, int out_size) {
    const float* inputs = (const float*)d_in[0];    // (B, S, D) fp32
    // d_in[1]: input_paddings (unused — all zeros)
    const int* lengths_raw = (const int*)d_in[2];   // (B,) int32 or int64
    float* out = (float*)d_out;

    fused_pack_kernel<<<(BB * SS) / RPB, NTHR>>>(inputs, lengths_raw, out,
                                                 (long long)out_size);
}